// round 14
// baseline (speedup 1.0000x reference)
#include <cuda_runtime.h>
#include <cstdint>
#include <math.h>

#define BB 64
#define SS 2048
#define HH 1024
#define K2 2048
#define NEG_BIG (-1e10f)

// ---- energy GEMM tiling ----
#define CM 128              // m rows per CTA
#define CN 256              // n cols per CTA
#define CK 64               // k per chunk
#define NKC (K2/CK)         // 32 chunks
#define ROWW 72             // row stride in words (64 data + 8 pad) — 8-bank row advance, conflict-free
#define ROWB (ROWW*4)       // 288 bytes
#define SA_BYTES (CM*ROWB)  // 36864
#define SB_BYTES (CN*ROWB)  // 73728
#define STAGE (SA_BYTES+SB_BYTES)   // 110592
#define SM_DV (2*STAGE)             // 221184
#define SM_TOTAL (SM_DV + HH*8)     // 229376

// scratch
__device__ float g_decf[BB * HH];
__device__ float g_energy[BB * SS];
__device__ float g_wt[HH * K2];     // Ws transposed [n][k], tf32-prerounded

// ---------------- helpers ----------------
__device__ __forceinline__ uint32_t smem_u32(const void* p) {
    uint32_t a;
    asm("{ .reg .u64 t; cvta.to.shared.u64 t, %1; cvt.u32.u64 %0, t; }" : "=r"(a) : "l"(p));
    return a;
}
#define CP_ASYNC16(dst, src) \
    asm volatile("cp.async.cg.shared.global [%0], [%1], 16;" :: "r"(dst), "l"(src))
#define CP_COMMIT() asm volatile("cp.async.commit_group;" ::: "memory")

__device__ __forceinline__ uint32_t f2tf32(float x) {
    uint32_t r;
    asm("cvt.rna.tf32.f32 %0, %1;" : "=r"(r) : "f"(x));
    return r;
}
__device__ __forceinline__ float tanha(float x) {
    float y;
    asm("tanh.approx.f32 %0, %1;" : "=f"(y) : "f"(x));
    return y;
}
__device__ __forceinline__ void mma_tf32(float* c, const uint32_t* a, const uint32_t* b) {
    asm volatile(
        "mma.sync.aligned.m16n8k8.row.col.f32.tf32.tf32.f32 "
        "{%0,%1,%2,%3}, {%4,%5,%6,%7}, {%8,%9}, {%0,%1,%2,%3};"
        : "+f"(c[0]), "+f"(c[1]), "+f"(c[2]), "+f"(c[3])
        : "r"(a[0]), "r"(a[1]), "r"(a[2]), "r"(a[3]), "r"(b[0]), "r"(b[1]));
}

// ---------------------------------------------------------------------------
// zero energy + context accumulators (graph replays re-run everything)
// ---------------------------------------------------------------------------
__global__ void zero_kernel(float* __restrict__ energy, float* __restrict__ ctx) {
    int i = blockIdx.x * blockDim.x + threadIdx.x;
    if (i < BB * SS) energy[i] = 0.0f;
    if (i < BB * K2) ctx[i] = 0.0f;
}

// ---------------------------------------------------------------------------
// transpose Ws [K2][H] -> Wt [H][K2], pre-rounded to tf32
// ---------------------------------------------------------------------------
__global__ void transpose_kernel(const float* __restrict__ Ws, float* __restrict__ Wt) {
    __shared__ float t[32][33];
    int k0 = blockIdx.x * 32, n0 = blockIdx.y * 32;
    for (int i = threadIdx.y; i < 32; i += 8)
        t[i][threadIdx.x] = Ws[(size_t)(k0 + i) * HH + n0 + threadIdx.x];
    __syncthreads();
    for (int i = threadIdx.y; i < 32; i += 8)
        Wt[(size_t)(n0 + i) * K2 + k0 + threadIdx.x] =
            __uint_as_float(f2tf32(t[threadIdx.x][i]));
}

// ---------------------------------------------------------------------------
// decf[b, n] = sum_k dh[b, k] * W_h[k, n]   (fp32 exact)
// ---------------------------------------------------------------------------
__global__ void decf_kernel(const float* __restrict__ dh, const float* __restrict__ Wh,
                            float* __restrict__ out) {
    int b = blockIdx.y;
    int n = blockIdx.x * 256 + threadIdx.x;
    const float* dhb = dh + b * HH;
    float acc = 0.0f;
#pragma unroll 4
    for (int k = 0; k < HH; k++) acc = fmaf(dhb[k], Wh[(size_t)k * HH + n], acc);
    out[b * HH + n] = acc;
}

// ---------------------------------------------------------------------------
// fused energy GEMM: tf32 mma.sync, tanh*v epilogue, atomic partial sums
// grid (4 n-tiles, 1024 m-tiles), 256 threads, double-buffered CK=64 chunks
// ---------------------------------------------------------------------------
__device__ __forceinline__ void fill_stage(uint32_t sb, int st, int kc, int tid,
                                           const float* Ag, const float* Bg) {
    uint32_t sA = sb + (uint32_t)st * STAGE;
    uint32_t sB = sA + SA_BYTES;
#pragma unroll
    for (int i = 0; i < 8; i++) {
        int seg = tid + i * 256;
        int row = seg >> 4, cc = seg & 15;
        CP_ASYNC16(sA + row * ROWB + cc * 16, Ag + (size_t)row * K2 + kc * CK + cc * 4);
    }
#pragma unroll
    for (int i = 0; i < 16; i++) {
        int seg = tid + i * 256;
        int row = seg >> 4, cc = seg & 15;
        CP_ASYNC16(sB + row * ROWB + cc * 16, Bg + (size_t)row * K2 + kc * CK + cc * 4);
    }
    CP_COMMIT();
}

__global__ __launch_bounds__(256, 1)
void energy_kernel(const float* __restrict__ enc, const float* __restrict__ wt,
                   const float* __restrict__ decf, const float* __restrict__ v,
                   float* __restrict__ energy) {
    extern __shared__ char smem[];
    const uint32_t sb = smem_u32(smem);
    const int tid = threadIdx.x;
    const int l = tid & 31, wid = tid >> 5;
    const int wm = wid >> 2;          // 0..1  (m)
    const int wn = wid & 3;           // 0..3  (n)
    const int mtile = blockIdx.y;
    const int m0 = mtile * CM;
    const int n0 = blockIdx.x * CN;
    const int b = mtile >> 4;         // 16 m-tiles per batch row

    // decf/v table
    float2* dv = (float2*)(smem + SM_DV);
    for (int i = tid; i < HH; i += 256)
        dv[i] = make_float2(decf[b * HH + i], v[i]);

    const float* Ag = enc + (size_t)m0 * K2;
    const float* Bg = wt + (size_t)n0 * K2;

    float acc[4][8][4];
#pragma unroll
    for (int mi = 0; mi < 4; mi++)
#pragma unroll
        for (int ni = 0; ni < 8; ni++)
#pragma unroll
            for (int r = 0; r < 4; r++) acc[mi][ni][r] = 0.0f;

    fill_stage(sb, 0, 0, tid, Ag, Bg);

#pragma unroll 1
    for (int kc = 0; kc < NKC; kc++) {
        const int st = kc & 1;
        if (kc + 1 < NKC) {
            fill_stage(sb, st ^ 1, kc + 1, tid, Ag, Bg);
            asm volatile("cp.async.wait_group 1;" ::: "memory");
        } else {
            asm volatile("cp.async.wait_group 0;" ::: "memory");
        }
        __syncthreads();

        const uint32_t sA = sb + (uint32_t)st * STAGE;
        const uint32_t sB = sA + SA_BYTES;
#pragma unroll
        for (int ks = 0; ks < 8; ks++) {
            uint32_t a[4][4];
#pragma unroll
            for (int mi = 0; mi < 4; mi++) {
                uint32_t r0 = (uint32_t)(wm * 64 + mi * 16 + (l >> 2));
                uint32_t ad = sA + (r0 * ROWW + ks * 8 + 2 * (l & 3)) * 4;
                // physical-k pairing: slots (c, c+4) <- phys (2c, 2c+1);
                // raw fp32 bits as tf32 operands (hardware reads tf32 subset)
                asm("ld.shared.v2.b32 {%0,%1}, [%2];"
                    : "=r"(a[mi][0]), "=r"(a[mi][2]) : "r"(ad));
                asm("ld.shared.v2.b32 {%0,%1}, [%2];"
                    : "=r"(a[mi][1]), "=r"(a[mi][3]) : "r"(ad + 8u * ROWB));
            }
            uint32_t bf[8][2];
#pragma unroll
            for (int ni = 0; ni < 8; ni++) {
                uint32_t rb = (uint32_t)(wn * 64 + ni * 8 + (l >> 2));
                uint32_t ad = sB + (rb * ROWW + ks * 8 + 2 * (l & 3)) * 4;
                asm("ld.shared.v2.b32 {%0,%1}, [%2];"
                    : "=r"(bf[ni][0]), "=r"(bf[ni][1]) : "r"(ad));
            }
#pragma unroll
            for (int mi = 0; mi < 4; mi++)
#pragma unroll
                for (int ni = 0; ni < 8; ni++)
                    mma_tf32(acc[mi][ni], a[mi], bf[ni]);
        }
        __syncthreads();
    }

    // epilogue: energy partial = sum_n tanh(acc + decf[n]) * v[n]
    float esum[8];
#pragma unroll
    for (int i = 0; i < 8; i++) esum[i] = 0.0f;
#pragma unroll
    for (int mi = 0; mi < 4; mi++)
#pragma unroll
        for (int ni = 0; ni < 8; ni++) {
            int n = n0 + wn * 64 + ni * 8 + 2 * (l & 3);
            float2 d0 = dv[n], d1 = dv[n + 1];
            esum[2 * mi] += tanha(acc[mi][ni][0] + d0.x) * d0.y
                          + tanha(acc[mi][ni][1] + d1.x) * d1.y;
            esum[2 * mi + 1] += tanha(acc[mi][ni][2] + d0.x) * d0.y
                              + tanha(acc[mi][ni][3] + d1.x) * d1.y;
        }
#pragma unroll
    for (int i = 0; i < 8; i++) {
        esum[i] += __shfl_xor_sync(0xffffffffu, esum[i], 1);
        esum[i] += __shfl_xor_sync(0xffffffffu, esum[i], 2);
    }
    if ((l & 3) == 0) {
        int rbase = m0 + wm * 64 + (l >> 2);
#pragma unroll
        for (int mi = 0; mi < 4; mi++) {
            atomicAdd(&energy[rbase + mi * 16], esum[2 * mi]);
            atomicAdd(&energy[rbase + mi * 16 + 8], esum[2 * mi + 1]);
        }
    }
}

// ---------------------------------------------------------------------------
// masked softmax over S per batch
// ---------------------------------------------------------------------------
__global__ void softmax_kernel(const float* __restrict__ energy,
                               const int* __restrict__ mask,
                               float* __restrict__ attn) {
    const int b = blockIdx.x;
    const int tid = threadIdx.x;
    __shared__ float red[256];
    float e[8];
#pragma unroll
    for (int i = 0; i < 8; i++) {
        int idx = tid + i * 256;
        float x = energy[(size_t)b * SS + idx];
        if (mask[(size_t)b * SS + idx] == 0) x = NEG_BIG;
        e[i] = x;
    }
    float m = e[0];
#pragma unroll
    for (int i = 1; i < 8; i++) m = fmaxf(m, e[i]);
    red[tid] = m;
    __syncthreads();
    for (int off = 128; off > 0; off >>= 1) {
        if (tid < off) red[tid] = fmaxf(red[tid], red[tid + off]);
        __syncthreads();
    }
    m = red[0];
    __syncthreads();
    float s = 0.0f;
#pragma unroll
    for (int i = 0; i < 8; i++) { e[i] = __expf(e[i] - m); s += e[i]; }
    red[tid] = s;
    __syncthreads();
    for (int off = 128; off > 0; off >>= 1) {
        if (tid < off) red[tid] += red[tid + off];
        __syncthreads();
    }
    float inv = 1.0f / red[0];
#pragma unroll
    for (int i = 0; i < 8; i++)
        attn[(size_t)b * SS + tid + i * 256] = e[i] * inv;
}

// ---------------------------------------------------------------------------
// context[b, e] += sum_{s in chunk} attn[b, s] * enc[b, s, e]
// grid (B, 8 s-chunks), 512 threads (one float4 column each)
// ---------------------------------------------------------------------------
__global__ void context_kernel(const float* __restrict__ attn,
                               const float* __restrict__ enc,
                               float* __restrict__ ctx) {
    const int b = blockIdx.x;
    const int s0 = blockIdx.y * (SS / 8);
    const int f4 = threadIdx.x;      // 0..511
    const float4* encb = (const float4*)(enc + (size_t)b * SS * K2);
    const float* ab = attn + (size_t)b * SS;
    float4 acc = make_float4(0.f, 0.f, 0.f, 0.f);
#pragma unroll 4
    for (int s = s0; s < s0 + SS / 8; s++) {
        float a = ab[s];
        float4 x = encb[(size_t)s * (K2 / 4) + f4];
        acc.x = fmaf(a, x.x, acc.x);
        acc.y = fmaf(a, x.y, acc.y);
        acc.z = fmaf(a, x.z, acc.z);
        acc.w = fmaf(a, x.w, acc.w);
    }
    float* c = ctx + (size_t)b * K2 + f4 * 4;
    atomicAdd(c + 0, acc.x);
    atomicAdd(c + 1, acc.y);
    atomicAdd(c + 2, acc.z);
    atomicAdd(c + 3, acc.w);
}

// ---------------------------------------------------------------------------
extern "C" void kernel_launch(void* const* d_in, const int* in_sizes, int n_in,
                              void* d_out, int out_size) {
    const float* dh   = (const float*)d_in[0];
    const float* enc  = (const float*)d_in[1];
    const int*   mask = (const int*)d_in[2];
    const float* Wh   = (const float*)d_in[3];
    const float* Ws   = (const float*)d_in[4];
    const float* v    = (const float*)d_in[5];

    float* ctx_out  = (float*)d_out;
    float* attn_out = (float*)d_out + (size_t)BB * K2;

    float *decf, *energy, *wt;
    cudaGetSymbolAddress((void**)&decf, g_decf);
    cudaGetSymbolAddress((void**)&energy, g_energy);
    cudaGetSymbolAddress((void**)&wt, g_wt);

    cudaFuncSetAttribute(energy_kernel,
                         cudaFuncAttributeMaxDynamicSharedMemorySize, SM_TOTAL);

    zero_kernel<<<(BB * SS + 255) / 256, 256>>>(energy, ctx_out);
    {
        dim3 g(K2 / 32, HH / 32);
        transpose_kernel<<<g, dim3(32, 8)>>>(Ws, wt);
    }
    {
        dim3 g(HH / 256, BB);
        decf_kernel<<<g, 256>>>(dh, Wh, decf);
    }
    {
        dim3 g(HH / CN, (BB * SS) / CM);   // (4, 1024), n fastest
        energy_kernel<<<g, 256, SM_TOTAL>>>(enc, wt, decf, v, energy);
    }
    softmax_kernel<<<BB, 256>>>(energy, mask, attn_out);
    {
        dim3 g(BB, 8);
        context_kernel<<<g, 512>>>(attn_out, enc, ctx_out);
    }
}

// round 17
// speedup vs baseline: 2.4347x; 2.4347x over previous
#include <cuda_runtime.h>
#include <cuda_fp16.h>
#include <cstdint>
#include <math.h>

#define BB 64
#define SS 2048
#define HH 1024
#define K2 2048
#define NEG_BIG (-1e10f)

// ---- energy GEMM tiling (fp16 operands, m16n8k16) ----
#define CM 128              // m rows per CTA
#define CN 256              // n cols per CTA
#define CK 64               // k halfs per chunk (128 B/row)
#define NKC (K2/CK)         // 32 chunks
#define ROWB 160            // row stride bytes (128 data + 32 pad) -> 8-bank row advance
#define SA_BYTES (CM*ROWB)  // 20480
#define SB_BYTES (CN*ROWB)  // 40960
#define STAGE (SA_BYTES+SB_BYTES)   // 61440
#define SM_DV (2*STAGE)             // 122880
#define SM_TOTAL (SM_DV + HH*8)     // 131072

// scratch
__device__ float  g_decf[BB * HH];
__device__ float  g_energy[BB * SS];
__device__ __half g_wth[HH * K2];            // Ws transposed [n][k] fp16
__device__ __half g_ench[(size_t)BB * SS * K2];  // enc in fp16 (512 MiB)

// ---------------- helpers ----------------
__device__ __forceinline__ uint32_t smem_u32(const void* p) {
    uint32_t a;
    asm("{ .reg .u64 t; cvta.to.shared.u64 t, %1; cvt.u32.u64 %0, t; }" : "=r"(a) : "l"(p));
    return a;
}
#define CP_ASYNC16(dst, src) \
    asm volatile("cp.async.cg.shared.global [%0], [%1], 16;" :: "r"(dst), "l"(src))
#define CP_COMMIT() asm volatile("cp.async.commit_group;" ::: "memory")

__device__ __forceinline__ float tanha(float x) {
    float y;
    asm("tanh.approx.f32 %0, %1;" : "=f"(y) : "f"(x));
    return y;
}
__device__ __forceinline__ void mma_f16(float* c, const uint32_t* a, const uint32_t* b) {
    asm volatile(
        "mma.sync.aligned.m16n8k16.row.col.f32.f16.f16.f32 "
        "{%0,%1,%2,%3}, {%4,%5,%6,%7}, {%8,%9}, {%0,%1,%2,%3};"
        : "+f"(c[0]), "+f"(c[1]), "+f"(c[2]), "+f"(c[3])
        : "r"(a[0]), "r"(a[1]), "r"(a[2]), "r"(a[3]), "r"(b[0]), "r"(b[1]));
}

// ---------------------------------------------------------------------------
// zero energy + context accumulators
// ---------------------------------------------------------------------------
__global__ void zero_kernel(float* __restrict__ energy, float* __restrict__ ctx) {
    int i = blockIdx.x * blockDim.x + threadIdx.x;
    if (i < BB * SS) energy[i] = 0.0f;
    if (i < BB * K2) ctx[i] = 0.0f;
}

// ---------------------------------------------------------------------------
// convert enc fp32 -> fp16 (one float4 -> 4 halfs per thread)
// ---------------------------------------------------------------------------
__global__ void convert_kernel(const float4* __restrict__ in, uint2* __restrict__ out) {
    size_t i = (size_t)blockIdx.x * blockDim.x + threadIdx.x;
    float4 x = in[i];
    __half2 h0 = __floats2half2_rn(x.x, x.y);
    __half2 h1 = __floats2half2_rn(x.z, x.w);
    uint2 o;
    o.x = *(uint32_t*)&h0;
    o.y = *(uint32_t*)&h1;
    out[i] = o;
}

// ---------------------------------------------------------------------------
// transpose Ws [K2][H] -> Wth [H][K2] fp16
// ---------------------------------------------------------------------------
__global__ void transpose_kernel(const float* __restrict__ Ws, __half* __restrict__ Wt) {
    __shared__ float t[32][33];
    int k0 = blockIdx.x * 32, n0 = blockIdx.y * 32;
    for (int i = threadIdx.y; i < 32; i += 8)
        t[i][threadIdx.x] = Ws[(size_t)(k0 + i) * HH + n0 + threadIdx.x];
    __syncthreads();
    for (int i = threadIdx.y; i < 32; i += 8)
        Wt[(size_t)(n0 + i) * K2 + k0 + threadIdx.x] = __float2half_rn(t[threadIdx.x][i]);
}

// ---------------------------------------------------------------------------
// decf[b, n] = sum_k dh[b, k] * W_h[k, n]   (fp32 exact)
// ---------------------------------------------------------------------------
__global__ void decf_kernel(const float* __restrict__ dh, const float* __restrict__ Wh,
                            float* __restrict__ out) {
    int b = blockIdx.y;
    int n = blockIdx.x * 256 + threadIdx.x;
    const float* dhb = dh + b * HH;
    float acc = 0.0f;
#pragma unroll 4
    for (int k = 0; k < HH; k++) acc = fmaf(dhb[k], Wh[(size_t)k * HH + n], acc);
    out[b * HH + n] = acc;
}

// ---------------------------------------------------------------------------
// fused energy GEMM (fp16 mma), tanh*v epilogue, atomic partial sums
// grid (4 n-tiles, 1024 m-tiles), 256 threads, double-buffered
// ---------------------------------------------------------------------------
__device__ __forceinline__ void fill_stage(uint32_t sb, int st, int kc, int tid,
                                           const __half* Ag, const __half* Bg) {
    uint32_t sA = sb + (uint32_t)st * STAGE;
    uint32_t sB = sA + SA_BYTES;
#pragma unroll
    for (int i = 0; i < 4; i++) {
        int seg = tid + i * 256;           // 1024 segs: 128 rows x 8 x 16B
        int row = seg >> 3, cc = seg & 7;
        CP_ASYNC16(sA + row * ROWB + cc * 16, Ag + (size_t)row * K2 + kc * CK + cc * 8);
    }
#pragma unroll
    for (int i = 0; i < 8; i++) {
        int seg = tid + i * 256;           // 2048 segs: 256 rows x 8 x 16B
        int row = seg >> 3, cc = seg & 7;
        CP_ASYNC16(sB + row * ROWB + cc * 16, Bg + (size_t)row * K2 + kc * CK + cc * 8);
    }
    CP_COMMIT();
}

__global__ __launch_bounds__(256, 1)
void energy_kernel(const __half* __restrict__ ench, const __half* __restrict__ wth,
                   const float* __restrict__ decf, const float* __restrict__ v,
                   float* __restrict__ energy) {
    extern __shared__ char smem[];
    const uint32_t sb = smem_u32(smem);
    const int tid = threadIdx.x;
    const int l = tid & 31, wid = tid >> 5;
    const int wm = wid >> 2;          // 0..1  (m)
    const int wn = wid & 3;           // 0..3  (n)
    const int mtile = blockIdx.y;
    const int m0 = mtile * CM;
    const int n0 = blockIdx.x * CN;
    const int b = mtile >> 4;         // 16 m-tiles per batch row

    float2* dv = (float2*)(smem + SM_DV);
    for (int i = tid; i < HH; i += 256)
        dv[i] = make_float2(decf[b * HH + i], v[i]);

    const __half* Ag = ench + (size_t)m0 * K2;
    const __half* Bg = wth + (size_t)n0 * K2;

    float acc[4][8][4];
#pragma unroll
    for (int mi = 0; mi < 4; mi++)
#pragma unroll
        for (int ni = 0; ni < 8; ni++)
#pragma unroll
            for (int r = 0; r < 4; r++) acc[mi][ni][r] = 0.0f;

    fill_stage(sb, 0, 0, tid, Ag, Bg);

#pragma unroll 1
    for (int kc = 0; kc < NKC; kc++) {
        const int st = kc & 1;
        if (kc + 1 < NKC) {
            fill_stage(sb, st ^ 1, kc + 1, tid, Ag, Bg);
            asm volatile("cp.async.wait_group 1;" ::: "memory");
        } else {
            asm volatile("cp.async.wait_group 0;" ::: "memory");
        }
        __syncthreads();

        const uint32_t sA = sb + (uint32_t)st * STAGE;
        const uint32_t sB = sA + SA_BYTES;
        // 4 k16-steps per chunk. Physical-k pairing: thread column c reads
        // phys halfs (4c..4c+3); slots a0/a2 (and b0/b1) take (4c,4c+1)/(4c+2,4c+3).
#pragma unroll
        for (int ks = 0; ks < 4; ks++) {
            uint32_t a[4][4];
#pragma unroll
            for (int mi = 0; mi < 4; mi++) {
                uint32_t r0 = (uint32_t)(wm * 64 + mi * 16 + (l >> 2));
                uint32_t ad = sA + r0 * ROWB + ks * 32 + (l & 3) * 8;
                asm("ld.shared.v2.b32 {%0,%1}, [%2];"
                    : "=r"(a[mi][0]), "=r"(a[mi][2]) : "r"(ad));
                asm("ld.shared.v2.b32 {%0,%1}, [%2];"
                    : "=r"(a[mi][1]), "=r"(a[mi][3]) : "r"(ad + 8u * ROWB));
            }
            uint32_t bf[8][2];
#pragma unroll
            for (int ni = 0; ni < 8; ni++) {
                uint32_t rb = (uint32_t)(wn * 64 + ni * 8 + (l >> 2));
                uint32_t bd = sB + rb * ROWB + ks * 32 + (l & 3) * 8;
                asm("ld.shared.v2.b32 {%0,%1}, [%2];"
                    : "=r"(bf[ni][0]), "=r"(bf[ni][1]) : "r"(bd));
            }
#pragma unroll
            for (int mi = 0; mi < 4; mi++)
#pragma unroll
                for (int ni = 0; ni < 8; ni++)
                    mma_f16(acc[mi][ni], a[mi], bf[ni]);
        }
        __syncthreads();
    }

    // epilogue: energy partial = sum_n tanh(acc + decf[n]) * v[n]
    float esum[8];
#pragma unroll
    for (int i = 0; i < 8; i++) esum[i] = 0.0f;
#pragma unroll
    for (int mi = 0; mi < 4; mi++)
#pragma unroll
        for (int ni = 0; ni < 8; ni++) {
            int n = n0 + wn * 64 + ni * 8 + 2 * (l & 3);
            float2 d0 = dv[n], d1 = dv[n + 1];
            esum[2 * mi] += tanha(acc[mi][ni][0] + d0.x) * d0.y
                          + tanha(acc[mi][ni][1] + d1.x) * d1.y;
            esum[2 * mi + 1] += tanha(acc[mi][ni][2] + d0.x) * d0.y
                              + tanha(acc[mi][ni][3] + d1.x) * d1.y;
        }
#pragma unroll
    for (int i = 0; i < 8; i++) {
        esum[i] += __shfl_xor_sync(0xffffffffu, esum[i], 1);
        esum[i] += __shfl_xor_sync(0xffffffffu, esum[i], 2);
    }
    if ((l & 3) == 0) {
        int rbase = m0 + wm * 64 + (l >> 2);
#pragma unroll
        for (int mi = 0; mi < 4; mi++) {
            atomicAdd(&energy[rbase + mi * 16], esum[2 * mi]);
            atomicAdd(&energy[rbase + mi * 16 + 8], esum[2 * mi + 1]);
        }
    }
}

// ---------------------------------------------------------------------------
// masked softmax over S per batch
// ---------------------------------------------------------------------------
__global__ void softmax_kernel(const float* __restrict__ energy,
                               const int* __restrict__ mask,
                               float* __restrict__ attn) {
    const int b = blockIdx.x;
    const int tid = threadIdx.x;
    __shared__ float red[256];
    float e[8];
#pragma unroll
    for (int i = 0; i < 8; i++) {
        int idx = tid + i * 256;
        float x = energy[(size_t)b * SS + idx];
        if (mask[(size_t)b * SS + idx] == 0) x = NEG_BIG;
        e[i] = x;
    }
    float m = e[0];
#pragma unroll
    for (int i = 1; i < 8; i++) m = fmaxf(m, e[i]);
    red[tid] = m;
    __syncthreads();
    for (int off = 128; off > 0; off >>= 1) {
        if (tid < off) red[tid] = fmaxf(red[tid], red[tid + off]);
        __syncthreads();
    }
    m = red[0];
    __syncthreads();
    float s = 0.0f;
#pragma unroll
    for (int i = 0; i < 8; i++) { e[i] = __expf(e[i] - m); s += e[i]; }
    red[tid] = s;
    __syncthreads();
    for (int off = 128; off > 0; off >>= 1) {
        if (tid < off) red[tid] += red[tid + off];
        __syncthreads();
    }
    float inv = 1.0f / red[0];
#pragma unroll
    for (int i = 0; i < 8; i++)
        attn[(size_t)b * SS + tid + i * 256] = e[i] * inv;
}

// ---------------------------------------------------------------------------
// context[b, e] += sum_{s in chunk} attn[b, s] * enc_h[b, s, e]   (fp16 enc)
// grid (B, 8 s-chunks), 512 threads: thread t handles halfs [4t, 4t+4)
// ---------------------------------------------------------------------------
__global__ void context_kernel(const float* __restrict__ attn,
                               const __half* __restrict__ ench,
                               float* __restrict__ ctx) {
    const int b = blockIdx.x;
    const int s0 = blockIdx.y * (SS / 8);
    const int t = threadIdx.x;       // 0..511
    const uint2* encb = (const uint2*)(ench + (size_t)b * SS * K2) + t;
    const float* ab = attn + (size_t)b * SS;
    float4 acc = make_float4(0.f, 0.f, 0.f, 0.f);
#pragma unroll 4
    for (int s = s0; s < s0 + SS / 8; s++) {
        float a = ab[s];
        uint2 w = encb[(size_t)s * (K2 / 4)];
        float2 x0 = __half22float2(*(const __half2*)&w.x);
        float2 x1 = __half22float2(*(const __half2*)&w.y);
        acc.x = fmaf(a, x0.x, acc.x);
        acc.y = fmaf(a, x0.y, acc.y);
        acc.z = fmaf(a, x1.x, acc.z);
        acc.w = fmaf(a, x1.y, acc.w);
    }
    float* c = ctx + (size_t)b * K2 + t * 4;
    atomicAdd(c + 0, acc.x);
    atomicAdd(c + 1, acc.y);
    atomicAdd(c + 2, acc.z);
    atomicAdd(c + 3, acc.w);
}

// ---------------------------------------------------------------------------
extern "C" void kernel_launch(void* const* d_in, const int* in_sizes, int n_in,
                              void* d_out, int out_size) {
    const float* dh   = (const float*)d_in[0];
    const float* enc  = (const float*)d_in[1];
    const int*   mask = (const int*)d_in[2];
    const float* Wh   = (const float*)d_in[3];
    const float* Ws   = (const float*)d_in[4];
    const float* v    = (const float*)d_in[5];

    float* ctx_out  = (float*)d_out;
    float* attn_out = (float*)d_out + (size_t)BB * K2;

    float *decf, *energy;
    __half *wth, *ench;
    cudaGetSymbolAddress((void**)&decf, g_decf);
    cudaGetSymbolAddress((void**)&energy, g_energy);
    cudaGetSymbolAddress((void**)&wth, g_wth);
    cudaGetSymbolAddress((void**)&ench, g_ench);

    cudaFuncSetAttribute(energy_kernel,
                         cudaFuncAttributeMaxDynamicSharedMemorySize, SM_TOTAL);

    zero_kernel<<<(BB * SS + 255) / 256, 256>>>(energy, ctx_out);
    {
        // 64*2048*2048 / 4 float4s per thread-item
        size_t n4 = (size_t)BB * SS * K2 / 4;
        convert_kernel<<<(unsigned)(n4 / 256), 256>>>((const float4*)enc, (uint2*)ench);
    }
    {
        dim3 g(K2 / 32, HH / 32);
        transpose_kernel<<<g, dim3(32, 8)>>>(Ws, wth);
    }
    {
        dim3 g(HH / 256, BB);
        decf_kernel<<<g, 256>>>(dh, Wh, decf);
    }
    {
        dim3 g(HH / CN, (BB * SS) / CM);   // (4, 1024), n fastest
        energy_kernel<<<g, 256, SM_TOTAL>>>(ench, wth, decf, v, energy);
    }
    softmax_kernel<<<BB, 256>>>(energy, mask, attn_out);
    {
        dim3 g(BB, 8);
        context_kernel<<<g, 512>>>(attn_out, ench, ctx_out);
    }
}